// round 1
// baseline (speedup 1.0000x reference)
#include <cuda_runtime.h>
#include <math.h>

#define DM   2560
#define NH   32
#define HD   80
#define BSZ  32      // keys per block
#define NB   32      // number of key blocks
#define KTOP 16
#define BATCH 2
#define SEQ  1024
#define NTOK (BATCH*SEQ)          // 2048
#define ATT_SCALE 0.1118033988749895f  // 80^-0.5

// ---------------- scratch (device globals; no runtime allocation) ----------------
__device__ float g_q   [NTOK * DM];
__device__ float g_k   [NTOK * DM];
__device__ float g_v   [NTOK * DM];
__device__ float g_comb[NTOK * DM];
__device__ float g_gh  [NTOK * (DM/2)];
__device__ float g_gates[NTOK * 3];
__device__ float g_kbar[BATCH * NH * NB * HD];
__device__ float g_Acomp[BATCH * NH * NB * DM];   // 4096 x 2560
__device__ float g_H1   [BATCH * NH * NB * 320];  // 4096 x 320
__device__ float g_kc   [BATCH * NH * NB * HD];
__device__ float g_vc   [BATCH * NH * NB * HD];
__device__ unsigned g_sel[BATCH * NH * SEQ];

__device__ __forceinline__ float gelu_f(float x) {
    return 0.5f * x * (1.0f + erff(x * 0.70710678118654752f));
}

// ---------------- generic SGEMM: C = act(A[MxK] @ B[KxN] + bias) ----------------
// BM=BN=128, BK=8, 256 threads, 8x8 per-thread tile. M % 128 == 0, K % 8 == 0.
__global__ void __launch_bounds__(256) sgemm_kernel(
    const float* __restrict__ A, const float* __restrict__ B,
    const float* __restrict__ bias, float* __restrict__ C,
    int M, int N, int K, int act)
{
    __shared__ float As[8][128];
    __shared__ float Bs[8][128];
    const int tid  = threadIdx.x;
    const int row0 = blockIdx.y * 128;
    const int col0 = blockIdx.x * 128;
    const int trow = (tid / 16) * 8;
    const int tcol = (tid % 16) * 8;

    float acc[8][8];
#pragma unroll
    for (int i = 0; i < 8; i++)
#pragma unroll
        for (int j = 0; j < 8; j++) acc[i][j] = 0.f;

    const int a_r = tid >> 1;
    const int a_c = (tid & 1) * 4;
    const int b_r = tid >> 5;          // 0..7
    const int b_c = (tid & 31) * 4;    // 0..124
    const int bc  = col0 + b_c;

    const float* Ap = A + (row0 + a_r) * K + a_c;
    const float* Bp = B + b_r * N + bc;

    for (int kk = 0; kk < K; kk += 8) {
        float4 av = *(const float4*)(Ap + kk);
        As[a_c + 0][a_r] = av.x;
        As[a_c + 1][a_r] = av.y;
        As[a_c + 2][a_r] = av.z;
        As[a_c + 3][a_r] = av.w;
        float4 bv = make_float4(0.f, 0.f, 0.f, 0.f);
        if (bc < N) bv = *(const float4*)(Bp + kk * N);
        *(float4*)&Bs[b_r][b_c] = bv;
        __syncthreads();
#pragma unroll
        for (int k2 = 0; k2 < 8; k2++) {
            float ar[8], br[8];
#pragma unroll
            for (int i = 0; i < 8; i++) ar[i] = As[k2][trow + i];
#pragma unroll
            for (int j = 0; j < 8; j++) br[j] = Bs[k2][tcol + j];
#pragma unroll
            for (int i = 0; i < 8; i++)
#pragma unroll
                for (int j = 0; j < 8; j++) acc[i][j] += ar[i] * br[j];
        }
        __syncthreads();
    }

#pragma unroll
    for (int i = 0; i < 8; i++) {
        int r = row0 + trow + i;
#pragma unroll
        for (int j = 0; j < 8; j++) {
            int c = col0 + tcol + j;
            if (c < N) {
                float val = acc[i][j] + bias[c];
                if (act == 1) val = gelu_f(val);
                C[r * N + c] = val;
            }
        }
    }
}

// ---------------- block-mean keys: kbar[b,h,n,d] = mean_j k[b, n*32+j, h*80+d] ----
__global__ void kbar_kernel(const float* __restrict__ k, float* __restrict__ kb)
{
    int idx = blockIdx.x * 256 + threadIdx.x;   // 163840 total
    int d = idx % HD;
    int n = (idx / HD) & 31;
    int h = (idx / (HD * 32)) & 31;
    int b = idx / (HD * 32 * 32);
    float s = 0.f;
#pragma unroll
    for (int j = 0; j < 32; j++)
        s += k[(b * SEQ + n * BSZ + j) * DM + h * HD + d];
    kb[idx] = s * 0.03125f;
}

// ------------- gather for compression MLP: A[(b,h,n)][j*80+d] = t[..]+pos --------
__global__ void gather_comp(const float* __restrict__ t, const float* __restrict__ pos,
                            float* __restrict__ A)
{
    int idx = blockIdx.x * 256 + threadIdx.x;   // 10485760 total
    int c = idx % DM;
    int row = idx / DM;                          // (b*32+h)*32+n
    int n = row & 31;
    int h = (row >> 5) & 31;
    int b = row >> 10;
    int j = c / HD, d = c - j * HD;
    A[idx] = t[(b * SEQ + n * BSZ + j) * DM + h * HD + d] + pos[c];
}

// ---------------- top-k block selection per query -> 32-bit mask -----------------
__global__ void __launch_bounds__(64) topk_kernel(
    const float* __restrict__ q, const float* __restrict__ kbar,
    unsigned* __restrict__ sel)
{
    __shared__ float Qs[64][81];
    __shared__ float Kb[32][80];
    const int q0 = blockIdx.x * 64;
    const int h = blockIdx.y, b = blockIdx.z;
    const int tid = threadIdx.x;

    for (int idx = tid; idx < 64 * 80; idx += 64) {
        int row = idx / 80, d = idx - row * 80;
        Qs[row][d] = q[(b * SEQ + q0 + row) * DM + h * HD + d];
    }
    for (int idx = tid; idx < 32 * 80; idx += 64) {
        int row = idx / 80, d = idx - row * 80;
        Kb[row][d] = kbar[((b * NH + h) * NB + row) * HD + d];
    }
    __syncthreads();

    float sc[32];
#pragma unroll
    for (int n = 0; n < 32; n++) {
        float s = 0.f;
        for (int d = 0; d < 80; d++) s += Qs[tid][d] * Kb[n][d];
        sc[n] = s;
    }
    unsigned mask = 0;
#pragma unroll
    for (int t = 0; t < KTOP; t++) {
        float best = -1e38f; int bi = 0;
#pragma unroll
        for (int n = 0; n < 32; n++) {
            if (!((mask >> n) & 1u) && sc[n] > best) { best = sc[n]; bi = n; }
        }
        mask |= (1u << bi);
    }
    sel[(b * NH + h) * SEQ + q0 + tid] = mask;
}

// ---------------- gates: sigmoid(gh @ W2 + b2), warp per (row,col) ---------------
__global__ void __launch_bounds__(256) gates_kernel(
    const float* __restrict__ gh, const float* __restrict__ W2,
    const float* __restrict__ b2, float* __restrict__ gates)
{
    int gw = (blockIdx.x * 256 + threadIdx.x) >> 5;   // global warp id
    int lane = threadIdx.x & 31;
    if (gw >= NTOK * 3) return;
    int row = gw / 3, col = gw - row * 3;
    float s = 0.f;
    for (int i = lane; i < DM / 2; i += 32)
        s += gh[row * (DM / 2) + i] * W2[i * 3 + col];
#pragma unroll
    for (int o = 16; o > 0; o >>= 1) s += __shfl_down_sync(0xffffffffu, s, o);
    if (lane == 0)
        gates[row * 3 + col] = 1.f / (1.f + __expf(-(s + b2[col])));
}

// ---------------- fused attention: window + selected + compressed ----------------
// One block = (b, h, 32 queries). 256 threads: qi = tid>>3 (query), r = tid&7.
// Single running-max flash pass; exp computed once per (q, key) and shared by
// the window and selection branches.
__global__ void __launch_bounds__(256) attn_kernel(
    const float* __restrict__ q, const float* __restrict__ k, const float* __restrict__ v,
    const float* __restrict__ kc, const float* __restrict__ vc,
    const unsigned* __restrict__ sel, const float* __restrict__ gates,
    float* __restrict__ comb)
{
    __shared__ float Qs[32][81];
    __shared__ float Ks[32][81];
    __shared__ float Vs[32][81];
    __shared__ float Ssm[32][33];

    const int q0 = blockIdx.x * 32;
    const int h  = blockIdx.y;
    const int b  = blockIdx.z;
    const int tid = threadIdx.x;
    const int qi = tid >> 3;
    const int r  = tid & 7;
    const int d0 = r * 10;
    const int j0 = r * 4;

    for (int idx = tid; idx < 32 * 80; idx += 256) {
        int row = idx / 80, d = idx - row * 80;
        Qs[row][d] = q[(b * SEQ + q0 + row) * DM + h * HD + d];
    }
    const unsigned msel = sel[(b * NH + h) * SEQ + q0 + qi];
    const int qrow = b * SEQ + q0 + qi;

    float mrun = -1e30f, lw = 0.f, ls = 0.f;
    float aw[10], asv[10];
#pragma unroll
    for (int i = 0; i < 10; i++) { aw[i] = 0.f; asv[i] = 0.f; }

    for (int n = 0; n < NB; n++) {
        __syncthreads();   // previous Vs fully consumed
        for (int idx = tid; idx < 32 * 80; idx += 256) {
            int row = idx / 80, d = idx - row * 80;
            int g = (b * SEQ + n * BSZ + row) * DM + h * HD + d;
            Ks[row][d] = k[g];
            Vs[row][d] = v[g];
        }
        __syncthreads();

        float s0 = 0.f, s1 = 0.f, s2 = 0.f, s3 = 0.f;
#pragma unroll
        for (int d = 0; d < 80; d++) {
            float qd = Qs[qi][d];
            s0 += qd * Ks[j0 + 0][d];
            s1 += qd * Ks[j0 + 1][d];
            s2 += qd * Ks[j0 + 2][d];
            s3 += qd * Ks[j0 + 3][d];
        }
        s0 *= ATT_SCALE; s1 *= ATT_SCALE; s2 *= ATT_SCALE; s3 *= ATT_SCALE;
        Ssm[qi][j0 + 0] = s0; Ssm[qi][j0 + 1] = s1;
        Ssm[qi][j0 + 2] = s2; Ssm[qi][j0 + 3] = s3;
        __syncwarp();
        float mb = -1e30f;
#pragma unroll
        for (int j = 0; j < 32; j++) mb = fmaxf(mb, Ssm[qi][j]);
        float mnew = fmaxf(mrun, mb);
        float alpha = __expf(mrun - mnew);
        __syncwarp();   // all 8 peers done reading row before overwrite
        Ssm[qi][j0 + 0] = __expf(s0 - mnew);
        Ssm[qi][j0 + 1] = __expf(s1 - mnew);
        Ssm[qi][j0 + 2] = __expf(s2 - mnew);
        Ssm[qi][j0 + 3] = __expf(s3 - mnew);
        __syncwarp();
        float ps = 0.f;
#pragma unroll
        for (int j = 0; j < 32; j++) ps += Ssm[qi][j];

        lw = lw * alpha + ps;
#pragma unroll
        for (int i = 0; i < 10; i++) aw[i] *= alpha;
#pragma unroll
        for (int j = 0; j < 32; j++) {
            float p = Ssm[qi][j];
#pragma unroll
            for (int i = 0; i < 10; i++) aw[i] += p * Vs[j][d0 + i];
        }
        ls *= alpha;
#pragma unroll
        for (int i = 0; i < 10; i++) asv[i] *= alpha;
        if ((msel >> n) & 1u) {
            ls += ps;
#pragma unroll
            for (int j = 0; j < 32; j++) {
                float p = Ssm[qi][j];
#pragma unroll
                for (int i = 0; i < 10; i++) asv[i] += p * Vs[j][d0 + i];
            }
        }
        mrun = mnew;
    }

    // ---- compressed branch (32 compressed K/V rows, full softmax) ----
    __syncthreads();
    for (int idx = tid; idx < 32 * 80; idx += 256) {
        int row = idx / 80, d = idx - row * 80;
        int g = ((b * NH + h) * NB + row) * HD + d;
        Ks[row][d] = kc[g];
        Vs[row][d] = vc[g];
    }
    __syncthreads();
    float c0 = 0.f, c1 = 0.f, c2 = 0.f, c3 = 0.f;
#pragma unroll
    for (int d = 0; d < 80; d++) {
        float qd = Qs[qi][d];
        c0 += qd * Ks[j0 + 0][d];
        c1 += qd * Ks[j0 + 1][d];
        c2 += qd * Ks[j0 + 2][d];
        c3 += qd * Ks[j0 + 3][d];
    }
    c0 *= ATT_SCALE; c1 *= ATT_SCALE; c2 *= ATT_SCALE; c3 *= ATT_SCALE;
    Ssm[qi][j0 + 0] = c0; Ssm[qi][j0 + 1] = c1;
    Ssm[qi][j0 + 2] = c2; Ssm[qi][j0 + 3] = c3;
    __syncwarp();
    float mc = -1e30f;
#pragma unroll
    for (int j = 0; j < 32; j++) mc = fmaxf(mc, Ssm[qi][j]);
    __syncwarp();
    Ssm[qi][j0 + 0] = __expf(c0 - mc);
    Ssm[qi][j0 + 1] = __expf(c1 - mc);
    Ssm[qi][j0 + 2] = __expf(c2 - mc);
    Ssm[qi][j0 + 3] = __expf(c3 - mc);
    __syncwarp();
    float lc = 0.f;
    float ac[10];
#pragma unroll
    for (int i = 0; i < 10; i++) ac[i] = 0.f;
#pragma unroll
    for (int j = 0; j < 32; j++) {
        float p = Ssm[qi][j];
        lc += p;
#pragma unroll
        for (int i = 0; i < 10; i++) ac[i] += p * Vs[j][d0 + i];
    }

    float gc = gates[qrow * 3 + 0];
    float gs = gates[qrow * 3 + 1];
    float gw = gates[qrow * 3 + 2];
    float ic  = gc / lc;
    float isf = gs / ls;
    float iwf = gw / lw;
#pragma unroll
    for (int i = 0; i < 10; i++)
        comb[qrow * DM + h * HD + d0 + i] = ic * ac[i] + isf * asv[i] + iwf * aw[i];
}

// ---------------------------------- launch ---------------------------------------
static inline int ceil_div(int a, int b) { return (a + b - 1) / b; }

extern "C" void kernel_launch(void* const* d_in, const int* in_sizes, int n_in,
                              void* d_out, int out_size)
{
    const float* hs       = (const float*)d_in[0];
    const float* Wq       = (const float*)d_in[1];
    const float* bq       = (const float*)d_in[2];
    const float* Wk       = (const float*)d_in[3];
    const float* bk       = (const float*)d_in[4];
    const float* Wv       = (const float*)d_in[5];
    const float* bv       = (const float*)d_in[6];
    const float* Wo       = (const float*)d_in[7];
    const float* bo       = (const float*)d_in[8];
    const float* comp_pos = (const float*)d_in[9];
    const float* comp_W1  = (const float*)d_in[10];
    const float* comp_b1  = (const float*)d_in[11];
    const float* comp_W2  = (const float*)d_in[12];
    const float* comp_b2  = (const float*)d_in[13];
    const float* gate_W1  = (const float*)d_in[14];
    const float* gate_b1  = (const float*)d_in[15];
    const float* gate_W2  = (const float*)d_in[16];
    const float* gate_b2  = (const float*)d_in[17];
    float* out = (float*)d_out;

    float *q, *k, *v, *comb, *gh, *gates, *kbar, *Acomp, *H1, *kc, *vc;
    unsigned* selp;
    cudaGetSymbolAddress((void**)&q,     g_q);
    cudaGetSymbolAddress((void**)&k,     g_k);
    cudaGetSymbolAddress((void**)&v,     g_v);
    cudaGetSymbolAddress((void**)&comb,  g_comb);
    cudaGetSymbolAddress((void**)&gh,    g_gh);
    cudaGetSymbolAddress((void**)&gates, g_gates);
    cudaGetSymbolAddress((void**)&kbar,  g_kbar);
    cudaGetSymbolAddress((void**)&Acomp, g_Acomp);
    cudaGetSymbolAddress((void**)&H1,    g_H1);
    cudaGetSymbolAddress((void**)&kc,    g_kc);
    cudaGetSymbolAddress((void**)&vc,    g_vc);
    cudaGetSymbolAddress((void**)&selp,  g_sel);

    // Q, K, V projections
    {
        dim3 grid(ceil_div(DM, 128), NTOK / 128);
        sgemm_kernel<<<grid, 256>>>(hs, Wq, bq, q, NTOK, DM, DM, 0);
        sgemm_kernel<<<grid, 256>>>(hs, Wk, bk, k, NTOK, DM, DM, 0);
        sgemm_kernel<<<grid, 256>>>(hs, Wv, bv, v, NTOK, DM, DM, 0);
    }
    // gate hidden + gates
    {
        dim3 grid(ceil_div(DM / 2, 128), NTOK / 128);
        sgemm_kernel<<<grid, 256>>>(hs, gate_W1, gate_b1, gh, NTOK, DM / 2, DM, 1);
        gates_kernel<<<ceil_div(NTOK * 3 * 32, 256), 256>>>(gh, gate_W2, gate_b2, gates);
    }
    // block-mean keys
    kbar_kernel<<<(BATCH * NH * NB * HD) / 256, 256>>>(k, kbar);

    // compression MLP for K
    {
        gather_comp<<<(BATCH * NH * NB * DM) / 256, 256>>>(k, comp_pos, Acomp);
        dim3 g1(ceil_div(320, 128), (BATCH * NH * NB) / 128);
        sgemm_kernel<<<g1, 256>>>(Acomp, comp_W1, comp_b1, H1, BATCH * NH * NB, 320, DM, 1);
        dim3 g2(1, (BATCH * NH * NB) / 128);
        sgemm_kernel<<<g2, 256>>>(H1, comp_W2, comp_b2, kc, BATCH * NH * NB, HD, 320, 0);
    }
    // compression MLP for V
    {
        gather_comp<<<(BATCH * NH * NB * DM) / 256, 256>>>(v, comp_pos, Acomp);
        dim3 g1(ceil_div(320, 128), (BATCH * NH * NB) / 128);
        sgemm_kernel<<<g1, 256>>>(Acomp, comp_W1, comp_b1, H1, BATCH * NH * NB, 320, DM, 1);
        dim3 g2(1, (BATCH * NH * NB) / 128);
        sgemm_kernel<<<g2, 256>>>(H1, comp_W2, comp_b2, vc, BATCH * NH * NB, HD, 320, 0);
    }

    // top-k block selection
    {
        dim3 grid(SEQ / 64, NH, BATCH);
        topk_kernel<<<grid, 64>>>(q, kbar, selp);
    }
    // fused attention (window + selected + compressed + gating)
    {
        dim3 grid(SEQ / 32, NH, BATCH);
        attn_kernel<<<grid, 256>>>(q, k, v, kc, vc, selp, gates, comb);
    }
    // output projection
    {
        dim3 grid(ceil_div(DM, 128), NTOK / 128);
        sgemm_kernel<<<grid, 256>>>(comb, Wo, bo, out, NTOK, DM, DM, 0);
    }
}

// round 2
// speedup vs baseline: 1.2847x; 1.2847x over previous
#include <cuda_runtime.h>
#include <math.h>

#define DM   2560
#define NH   32
#define HD   80
#define BSZ  32      // keys per block
#define NB   32      // number of key blocks
#define KTOP 16
#define BATCH 2
#define SEQ  1024
#define NTOK (BATCH*SEQ)          // 2048
#define ATT_SCALE 0.1118033988749895f  // 80^-0.5

// ---------------- scratch (device globals; no runtime allocation) ----------------
__device__ float g_q   [NTOK * DM];
__device__ float g_k   [NTOK * DM];
__device__ float g_v   [NTOK * DM];
__device__ float g_comb[NTOK * DM];
__device__ float g_gh  [NTOK * (DM/2)];
__device__ float g_gates[NTOK * 3];
__device__ float g_kbar[BATCH * NH * NB * HD];
__device__ float g_Acomp[BATCH * NH * NB * DM];   // 4096 x 2560
__device__ float g_H1   [BATCH * NH * NB * 320];  // 4096 x 320
__device__ float g_kc   [BATCH * NH * NB * HD];
__device__ float g_vc   [BATCH * NH * NB * HD];
__device__ unsigned g_sel[BATCH * NH * SEQ];

__device__ __forceinline__ float gelu_f(float x) {
    return 0.5f * x * (1.0f + erff(x * 0.70710678118654752f));
}

// ---------------- SGEMM v2: C = act(A[MxK] @ B[KxN] + bias) ----------------------
// 128x128 tile, BK=16, 256 threads, 8x8/thread, double-buffered smem with
// global->reg prefetch. Requires M%128==0, K%16==0. N tail handled by guards.
__global__ void __launch_bounds__(256, 2) sgemm_kernel(
    const float* __restrict__ A, const float* __restrict__ B,
    const float* __restrict__ bias, float* __restrict__ C,
    int M, int N, int K, int act)
{
    __shared__ float As[2][16][132];   // transposed: As[k][row]
    __shared__ float Bs[2][16][128];   // Bs[k][col]

    const int tid  = threadIdx.x;
    const int row0 = blockIdx.y * 128;
    const int col0 = blockIdx.x * 128;
    const int trow = (tid >> 4) * 8;   // 0..120
    const int tcol = (tid & 15) * 8;   // 0..120

    // load mapping: 512 float4 per tile per matrix, 2 per thread
    const int a_row = tid >> 2;          // 0..63 (+64 for i=1)
    const int a_k   = (tid & 3) * 4;     // 0,4,8,12
    const int b_k   = tid >> 5;          // 0..7 (+8 for i=1)
    const int b_col = (tid & 31) * 4;    // 0..124
    const int gcol  = col0 + b_col;
    const bool bok  = (gcol < N);

    float acc[8][8];
#pragma unroll
    for (int i = 0; i < 8; i++)
#pragma unroll
        for (int j = 0; j < 8; j++) acc[i][j] = 0.f;

    float4 aReg[2], bReg[2];
    const int ntiles = K / 16;

    // prefetch tile 0 into regs, store to buffer 0
#pragma unroll
    for (int i = 0; i < 2; i++) {
        aReg[i] = *(const float4*)&A[(row0 + a_row + i * 64) * K + a_k];
        bReg[i] = bok ? *(const float4*)&B[(b_k + i * 8) * N + gcol]
                      : make_float4(0.f, 0.f, 0.f, 0.f);
    }
#pragma unroll
    for (int i = 0; i < 2; i++) {
        As[0][a_k + 0][a_row + i * 64] = aReg[i].x;
        As[0][a_k + 1][a_row + i * 64] = aReg[i].y;
        As[0][a_k + 2][a_row + i * 64] = aReg[i].z;
        As[0][a_k + 3][a_row + i * 64] = aReg[i].w;
        *(float4*)&Bs[0][b_k + i * 8][b_col] = bReg[i];
    }
    __syncthreads();

    int buf = 0;
    for (int t = 0; t < ntiles; t++) {
        if (t + 1 < ntiles) {
            const int koff = (t + 1) * 16;
#pragma unroll
            for (int i = 0; i < 2; i++) {
                aReg[i] = *(const float4*)&A[(row0 + a_row + i * 64) * K + koff + a_k];
                bReg[i] = bok ? *(const float4*)&B[(koff + b_k + i * 8) * N + gcol]
                              : make_float4(0.f, 0.f, 0.f, 0.f);
            }
        }
#pragma unroll
        for (int k = 0; k < 16; k++) {
            float ar[8], br[8];
            *(float4*)&ar[0] = *(const float4*)&As[buf][k][trow];
            *(float4*)&ar[4] = *(const float4*)&As[buf][k][trow + 4];
            *(float4*)&br[0] = *(const float4*)&Bs[buf][k][tcol];
            *(float4*)&br[4] = *(const float4*)&Bs[buf][k][tcol + 4];
#pragma unroll
            for (int i = 0; i < 8; i++)
#pragma unroll
                for (int j = 0; j < 8; j++) acc[i][j] += ar[i] * br[j];
        }
        if (t + 1 < ntiles) {
            const int nb = buf ^ 1;
#pragma unroll
            for (int i = 0; i < 2; i++) {
                As[nb][a_k + 0][a_row + i * 64] = aReg[i].x;
                As[nb][a_k + 1][a_row + i * 64] = aReg[i].y;
                As[nb][a_k + 2][a_row + i * 64] = aReg[i].z;
                As[nb][a_k + 3][a_row + i * 64] = aReg[i].w;
                *(float4*)&Bs[nb][b_k + i * 8][b_col] = bReg[i];
            }
            __syncthreads();
            buf = nb;
        }
    }

    // epilogue
    if (col0 + 128 <= N) {
        float bb[8];
#pragma unroll
        for (int j = 0; j < 8; j++) bb[j] = bias[col0 + tcol + j];
#pragma unroll
        for (int i = 0; i < 8; i++) {
            const int r = row0 + trow + i;
            float o[8];
#pragma unroll
            for (int j = 0; j < 8; j++) {
                float val = acc[i][j] + bb[j];
                o[j] = (act == 1) ? gelu_f(val) : val;
            }
            *(float4*)&C[r * N + col0 + tcol]     = *(float4*)&o[0];
            *(float4*)&C[r * N + col0 + tcol + 4] = *(float4*)&o[4];
        }
    } else {
#pragma unroll
        for (int i = 0; i < 8; i++) {
            const int r = row0 + trow + i;
#pragma unroll
            for (int j = 0; j < 8; j++) {
                const int c = col0 + tcol + j;
                if (c < N) {
                    float val = acc[i][j] + bias[c];
                    if (act == 1) val = gelu_f(val);
                    C[r * N + c] = val;
                }
            }
        }
    }
}

// ---------------- block-mean keys ------------------------------------------------
__global__ void kbar_kernel(const float* __restrict__ k, float* __restrict__ kb)
{
    int idx = blockIdx.x * 256 + threadIdx.x;   // 163840 total
    int d = idx % HD;
    int n = (idx / HD) & 31;
    int h = (idx / (HD * 32)) & 31;
    int b = idx / (HD * 32 * 32);
    float s = 0.f;
#pragma unroll
    for (int j = 0; j < 32; j++)
        s += k[(b * SEQ + n * BSZ + j) * DM + h * HD + d];
    kb[idx] = s * 0.03125f;
}

// ------------- gather for compression MLP ---------------------------------------
__global__ void gather_comp(const float* __restrict__ t, const float* __restrict__ pos,
                            float* __restrict__ A)
{
    int idx = blockIdx.x * 256 + threadIdx.x;   // 10485760 total
    int c = idx % DM;
    int row = idx / DM;                          // (b*32+h)*32+n
    int n = row & 31;
    int h = (row >> 5) & 31;
    int b = row >> 10;
    int j = c / HD, d = c - j * HD;
    A[idx] = t[(b * SEQ + n * BSZ + j) * DM + h * HD + d] + pos[c];
}

// ---------------- top-k block selection -------------------------------------------
__global__ void __launch_bounds__(64) topk_kernel(
    const float* __restrict__ q, const float* __restrict__ kbar,
    unsigned* __restrict__ sel)
{
    __shared__ float Qs[64][84];
    __shared__ float Kb[32][84];
    const int q0 = blockIdx.x * 64;
    const int h = blockIdx.y, b = blockIdx.z;
    const int tid = threadIdx.x;

    for (int idx = tid; idx < 64 * 20; idx += 64) {
        int row = idx / 20, d4 = idx - row * 20;
        *(float4*)&Qs[row][d4 * 4] =
            *(const float4*)&q[(b * SEQ + q0 + row) * DM + h * HD + d4 * 4];
    }
    for (int idx = tid; idx < 32 * 20; idx += 64) {
        int row = idx / 20, d4 = idx - row * 20;
        *(float4*)&Kb[row][d4 * 4] =
            *(const float4*)&kbar[((b * NH + h) * NB + row) * HD + d4 * 4];
    }
    __syncthreads();

    float sc[32];
#pragma unroll
    for (int n = 0; n < 32; n++) {
        float s = 0.f;
        for (int d4 = 0; d4 < 20; d4++) {
            float4 qv = *(const float4*)&Qs[tid][d4 * 4];
            float4 kv = *(const float4*)&Kb[n][d4 * 4];
            s += qv.x * kv.x + qv.y * kv.y + qv.z * kv.z + qv.w * kv.w;
        }
        sc[n] = s;
    }
    unsigned mask = 0;
#pragma unroll
    for (int t = 0; t < KTOP; t++) {
        float best = -1e38f; int bi = 0;
#pragma unroll
        for (int n = 0; n < 32; n++) {
            if (!((mask >> n) & 1u) && sc[n] > best) { best = sc[n]; bi = n; }
        }
        mask |= (1u << bi);
    }
    sel[(b * NH + h) * SEQ + q0 + tid] = mask;
}

// ---------------- gates ------------------------------------------------------------
__global__ void __launch_bounds__(256) gates_kernel(
    const float* __restrict__ gh, const float* __restrict__ W2,
    const float* __restrict__ b2, float* __restrict__ gates)
{
    int gw = (blockIdx.x * 256 + threadIdx.x) >> 5;   // global warp id
    int lane = threadIdx.x & 31;
    if (gw >= NTOK * 3) return;
    int row = gw / 3, col = gw - row * 3;
    float s = 0.f;
    for (int i = lane; i < DM / 2; i += 32)
        s += gh[row * (DM / 2) + i] * W2[i * 3 + col];
#pragma unroll
    for (int o = 16; o > 0; o >>= 1) s += __shfl_down_sync(0xffffffffu, s, o);
    if (lane == 0)
        gates[row * 3 + col] = 1.f / (1.f + __expf(-(s + b2[col])));
}

// ---------------- fused attention: window + selected + compressed ----------------
// One block = (b, h, 32 queries). 256 threads: qi = tid>>3 (query), r = tid&7.
// Single flash pass; exp computed once per (q,key); V read ONCE serves both the
// window branch and (via fsel 0/1 FMA) the selection branch.
__global__ void __launch_bounds__(256) attn_kernel(
    const float* __restrict__ q, const float* __restrict__ k, const float* __restrict__ v,
    const float* __restrict__ kc, const float* __restrict__ vc,
    const unsigned* __restrict__ sel, const float* __restrict__ gates,
    float* __restrict__ comb)
{
    __shared__ float Qs[32][84];
    __shared__ float Ks[32][84];
    __shared__ float Vs[32][84];
    __shared__ float Ssm[32][36];

    const int q0 = blockIdx.x * 32;
    const int h  = blockIdx.y;
    const int b  = blockIdx.z;
    const int tid = threadIdx.x;
    const int qi = tid >> 3;
    const int r  = tid & 7;
    const int d0 = r * 10;
    const int j0 = r * 4;

    for (int idx = tid; idx < 32 * 20; idx += 256) {
        int row = idx / 20, d4 = idx - row * 20;
        *(float4*)&Qs[row][d4 * 4] =
            *(const float4*)&q[(b * SEQ + q0 + row) * DM + h * HD + d4 * 4];
    }
    const unsigned msel = sel[(b * NH + h) * SEQ + q0 + qi];
    const int qrow = b * SEQ + q0 + qi;

    float mrun = -1e30f, lw = 0.f, ls = 0.f;
    float aw[10], asv[10];
#pragma unroll
    for (int i = 0; i < 10; i++) { aw[i] = 0.f; asv[i] = 0.f; }

    for (int n = 0; n < NB; n++) {
        __syncthreads();   // previous Ks/Vs fully consumed
        for (int idx = tid; idx < 32 * 20; idx += 256) {
            int row = idx / 20, d4 = idx - row * 20;
            int g = (b * SEQ + n * BSZ + row) * DM + h * HD + d4 * 4;
            *(float4*)&Ks[row][d4 * 4] = *(const float4*)&k[g];
            *(float4*)&Vs[row][d4 * 4] = *(const float4*)&v[g];
        }
        __syncthreads();

        float s0 = 0.f, s1 = 0.f, s2 = 0.f, s3 = 0.f;
#pragma unroll
        for (int d4 = 0; d4 < 20; d4++) {
            float4 qv = *(const float4*)&Qs[qi][d4 * 4];
            float4 k0 = *(const float4*)&Ks[j0 + 0][d4 * 4];
            float4 k1 = *(const float4*)&Ks[j0 + 1][d4 * 4];
            float4 k2 = *(const float4*)&Ks[j0 + 2][d4 * 4];
            float4 k3 = *(const float4*)&Ks[j0 + 3][d4 * 4];
            s0 += qv.x * k0.x + qv.y * k0.y + qv.z * k0.z + qv.w * k0.w;
            s1 += qv.x * k1.x + qv.y * k1.y + qv.z * k1.z + qv.w * k1.w;
            s2 += qv.x * k2.x + qv.y * k2.y + qv.z * k2.z + qv.w * k2.w;
            s3 += qv.x * k3.x + qv.y * k3.y + qv.z * k3.z + qv.w * k3.w;
        }
        s0 *= ATT_SCALE; s1 *= ATT_SCALE; s2 *= ATT_SCALE; s3 *= ATT_SCALE;
        *(float4*)&Ssm[qi][j0] = make_float4(s0, s1, s2, s3);
        __syncwarp();
        float mb = -1e30f;
#pragma unroll
        for (int j4 = 0; j4 < 8; j4++) {
            float4 t4 = *(const float4*)&Ssm[qi][j4 * 4];
            mb = fmaxf(mb, fmaxf(fmaxf(t4.x, t4.y), fmaxf(t4.z, t4.w)));
        }
        float mnew = fmaxf(mrun, mb);
        float alpha = __expf(mrun - mnew);
        __syncwarp();   // all 8 peers done reading raw scores before overwrite
        *(float4*)&Ssm[qi][j0] = make_float4(__expf(s0 - mnew), __expf(s1 - mnew),
                                             __expf(s2 - mnew), __expf(s3 - mnew));
        __syncwarp();

        float ps = 0.f;
        const float fsel = ((msel >> n) & 1u) ? 1.f : 0.f;
        lw *= alpha; ls *= alpha;
#pragma unroll
        for (int i = 0; i < 10; i++) { aw[i] *= alpha; asv[i] *= alpha; }
#pragma unroll
        for (int j4 = 0; j4 < 8; j4++) {
            float4 p4 = *(const float4*)&Ssm[qi][j4 * 4];
            ps += p4.x + p4.y + p4.z + p4.w;
            float pj[4] = {p4.x, p4.y, p4.z, p4.w};
#pragma unroll
            for (int jj = 0; jj < 4; jj++) {
                const float p  = pj[jj];
                const float pf = p * fsel;
                const int   j  = j4 * 4 + jj;
#pragma unroll
                for (int i2 = 0; i2 < 5; i2++) {
                    float2 v2 = *(const float2*)&Vs[j][d0 + 2 * i2];
                    aw[2 * i2]      += p  * v2.x;
                    aw[2 * i2 + 1]  += p  * v2.y;
                    asv[2 * i2]     += pf * v2.x;
                    asv[2 * i2 + 1] += pf * v2.y;
                }
            }
        }
        lw += ps;
        ls += fsel * ps;
        mrun = mnew;
    }

    // ---- compressed branch (32 compressed K/V rows, full softmax) ----
    __syncthreads();
    for (int idx = tid; idx < 32 * 20; idx += 256) {
        int row = idx / 20, d4 = idx - row * 20;
        int g = ((b * NH + h) * NB + row) * HD + d4 * 4;
        *(float4*)&Ks[row][d4 * 4] = *(const float4*)&kc[g];
        *(float4*)&Vs[row][d4 * 4] = *(const float4*)&vc[g];
    }
    __syncthreads();
    float c0 = 0.f, c1 = 0.f, c2 = 0.f, c3 = 0.f;
#pragma unroll
    for (int d4 = 0; d4 < 20; d4++) {
        float4 qv = *(const float4*)&Qs[qi][d4 * 4];
        float4 k0 = *(const float4*)&Ks[j0 + 0][d4 * 4];
        float4 k1 = *(const float4*)&Ks[j0 + 1][d4 * 4];
        float4 k2 = *(const float4*)&Ks[j0 + 2][d4 * 4];
        float4 k3 = *(const float4*)&Ks[j0 + 3][d4 * 4];
        c0 += qv.x * k0.x + qv.y * k0.y + qv.z * k0.z + qv.w * k0.w;
        c1 += qv.x * k1.x + qv.y * k1.y + qv.z * k1.z + qv.w * k1.w;
        c2 += qv.x * k2.x + qv.y * k2.y + qv.z * k2.z + qv.w * k2.w;
        c3 += qv.x * k3.x + qv.y * k3.y + qv.z * k3.z + qv.w * k3.w;
    }
    c0 *= ATT_SCALE; c1 *= ATT_SCALE; c2 *= ATT_SCALE; c3 *= ATT_SCALE;
    *(float4*)&Ssm[qi][j0] = make_float4(c0, c1, c2, c3);
    __syncwarp();
    float mc = -1e30f;
#pragma unroll
    for (int j4 = 0; j4 < 8; j4++) {
        float4 t4 = *(const float4*)&Ssm[qi][j4 * 4];
        mc = fmaxf(mc, fmaxf(fmaxf(t4.x, t4.y), fmaxf(t4.z, t4.w)));
    }
    __syncwarp();
    *(float4*)&Ssm[qi][j0] = make_float4(__expf(c0 - mc), __expf(c1 - mc),
                                         __expf(c2 - mc), __expf(c3 - mc));
    __syncwarp();
    float lc = 0.f;
    float ac[10];
#pragma unroll
    for (int i = 0; i < 10; i++) ac[i] = 0.f;
#pragma unroll
    for (int j4 = 0; j4 < 8; j4++) {
        float4 p4 = *(const float4*)&Ssm[qi][j4 * 4];
        lc += p4.x + p4.y + p4.z + p4.w;
        float pj[4] = {p4.x, p4.y, p4.z, p4.w};
#pragma unroll
        for (int jj = 0; jj < 4; jj++) {
            const float p = pj[jj];
            const int   j = j4 * 4 + jj;
#pragma unroll
            for (int i2 = 0; i2 < 5; i2++) {
                float2 v2 = *(const float2*)&Vs[j][d0 + 2 * i2];
                ac[2 * i2]     += p * v2.x;
                ac[2 * i2 + 1] += p * v2.y;
            }
        }
    }

    const float gc = gates[qrow * 3 + 0];
    const float gs = gates[qrow * 3 + 1];
    const float gw = gates[qrow * 3 + 2];
    const float ic  = gc / lc;
    const float isf = gs / ls;
    const float iwf = gw / lw;
#pragma unroll
    for (int i = 0; i < 10; i++)
        comb[qrow * DM + h * HD + d0 + i] = ic * ac[i] + isf * asv[i] + iwf * aw[i];
}

// ---------------------------------- launch ---------------------------------------
static inline int ceil_div(int a, int b) { return (a + b - 1) / b; }

extern "C" void kernel_launch(void* const* d_in, const int* in_sizes, int n_in,
                              void* d_out, int out_size)
{
    const float* hs       = (const float*)d_in[0];
    const float* Wq       = (const float*)d_in[1];
    const float* bq       = (const float*)d_in[2];
    const float* Wk       = (const float*)d_in[3];
    const float* bk       = (const float*)d_in[4];
    const float* Wv       = (const float*)d_in[5];
    const float* bv       = (const float*)d_in[6];
    const float* Wo       = (const float*)d_in[7];
    const float* bo       = (const float*)d_in[8];
    const float* comp_pos = (const float*)d_in[9];
    const float* comp_W1  = (const float*)d_in[10];
    const float* comp_b1  = (const float*)d_in[11];
    const float* comp_W2  = (const float*)d_in[12];
    const float* comp_b2  = (const float*)d_in[13];
    const float* gate_W1  = (const float*)d_in[14];
    const float* gate_b1  = (const float*)d_in[15];
    const float* gate_W2  = (const float*)d_in[16];
    const float* gate_b2  = (const float*)d_in[17];
    float* out = (float*)d_out;

    float *q, *k, *v, *comb, *gh, *gates, *kbar, *Acomp, *H1, *kc, *vc;
    unsigned* selp;
    cudaGetSymbolAddress((void**)&q,     g_q);
    cudaGetSymbolAddress((void**)&k,     g_k);
    cudaGetSymbolAddress((void**)&v,     g_v);
    cudaGetSymbolAddress((void**)&comb,  g_comb);
    cudaGetSymbolAddress((void**)&gh,    g_gh);
    cudaGetSymbolAddress((void**)&gates, g_gates);
    cudaGetSymbolAddress((void**)&kbar,  g_kbar);
    cudaGetSymbolAddress((void**)&Acomp, g_Acomp);
    cudaGetSymbolAddress((void**)&H1,    g_H1);
    cudaGetSymbolAddress((void**)&kc,    g_kc);
    cudaGetSymbolAddress((void**)&vc,    g_vc);
    cudaGetSymbolAddress((void**)&selp,  g_sel);

    // Q, K, V projections
    {
        dim3 grid(DM / 128, NTOK / 128);
        sgemm_kernel<<<grid, 256>>>(hs, Wq, bq, q, NTOK, DM, DM, 0);
        sgemm_kernel<<<grid, 256>>>(hs, Wk, bk, k, NTOK, DM, DM, 0);
        sgemm_kernel<<<grid, 256>>>(hs, Wv, bv, v, NTOK, DM, DM, 0);
    }
    // gate hidden + gates
    {
        dim3 grid((DM / 2) / 128, NTOK / 128);
        sgemm_kernel<<<grid, 256>>>(hs, gate_W1, gate_b1, gh, NTOK, DM / 2, DM, 1);
        gates_kernel<<<ceil_div(NTOK * 3 * 32, 256), 256>>>(gh, gate_W2, gate_b2, gates);
    }
    // block-mean keys
    kbar_kernel<<<(BATCH * NH * NB * HD) / 256, 256>>>(k, kbar);

    // compression MLP for K
    {
        gather_comp<<<(BATCH * NH * NB * DM) / 256, 256>>>(k, comp_pos, Acomp);
        dim3 g1(ceil_div(320, 128), (BATCH * NH * NB) / 128);
        sgemm_kernel<<<g1, 256>>>(Acomp, comp_W1, comp_b1, H1, BATCH * NH * NB, 320, DM, 1);
        dim3 g2(1, (BATCH * NH * NB) / 128);
        sgemm_kernel<<<g2, 256>>>(H1, comp_W2, comp_b2, kc, BATCH * NH * NB, HD, 320, 0);
    }
    // compression MLP for V
    {
        gather_comp<<<(BATCH * NH * NB * DM) / 256, 256>>>(v, comp_pos, Acomp);
        dim3 g1(ceil_div(320, 128), (BATCH * NH * NB) / 128);
        sgemm_kernel<<<g1, 256>>>(Acomp, comp_W1, comp_b1, H1, BATCH * NH * NB, 320, DM, 1);
        dim3 g2(1, (BATCH * NH * NB) / 128);
        sgemm_kernel<<<g2, 256>>>(H1, comp_W2, comp_b2, vc, BATCH * NH * NB, HD, 320, 0);
    }

    // top-k block selection
    {
        dim3 grid(SEQ / 64, NH, BATCH);
        topk_kernel<<<grid, 64>>>(q, kbar, selp);
    }
    // fused attention (window + selected + compressed + gating)
    {
        dim3 grid(SEQ / 32, NH, BATCH);
        attn_kernel<<<grid, 256>>>(q, k, v, kc, vc, selp, gates, comb);
    }
    // output projection
    {
        dim3 grid(DM / 128, NTOK / 128);
        sgemm_kernel<<<grid, 256>>>(comb, Wo, bo, out, NTOK, DM, DM, 0);
    }
}